// round 1
// baseline (speedup 1.0000x reference)
#include <cuda_runtime.h>
#include <mma.h>
#include <math.h>

using namespace nvcuda;

// ---------------------------------------------------------------------------
// Problem constants (from reference: B=1, T=2048, DIM=1024, HID=4096, E=8,
// TOPK=2 but only top-1 routed expert is used; ALPHA=2)
// ---------------------------------------------------------------------------
#define TOK   2048
#define DIMK  1024
#define HIDN  4096
#define NEXP  7          // routed experts
#define NE_ALL 8
#define ALPHA_C 2.0f

// GEMM tile config
#define BM 128
#define BN 64
#define BK 16
#define NTHREADS 256

// ---------------------------------------------------------------------------
// Scratch (device globals; no allocation allowed in kernel_launch)
// ---------------------------------------------------------------------------
__device__ int   g_eidx[TOK];
__device__ float g_scale[TOK];
__device__ int   g_perm[TOK];
__device__ int   g_off[NEXP + 1];
__device__ float g_hr[(size_t)TOK * HIDN];   // routed hidden (perm-position rows)
__device__ float g_hs[(size_t)TOK * HIDN];   // shared hidden (token rows)

// ---------------------------------------------------------------------------
// Router: fp32-exact logits, softmax top-1.  One warp per token.
// w_router is [DIM, 8] row-major -> row d holds 8 consecutive expert weights.
// ---------------------------------------------------------------------------
__global__ void router_kernel(const float* __restrict__ x,
                              const float* __restrict__ wr) {
    int gw   = (blockIdx.x * blockDim.x + threadIdx.x) >> 5;
    int lane = threadIdx.x & 31;
    if (gw >= TOK) return;
    const float* xr = x + (size_t)gw * DIMK;

    float acc[NE_ALL];
#pragma unroll
    for (int e = 0; e < NE_ALL; e++) acc[e] = 0.f;

    for (int d = lane; d < DIMK; d += 32) {
        float xv = xr[d];
        const float4* w4 = reinterpret_cast<const float4*>(wr + (size_t)d * NE_ALL);
        float4 w0 = w4[0];
        float4 w1 = w4[1];
        acc[0] += xv * w0.x; acc[1] += xv * w0.y;
        acc[2] += xv * w0.z; acc[3] += xv * w0.w;
        acc[4] += xv * w1.x; acc[5] += xv * w1.y;
        acc[6] += xv * w1.z; acc[7] += xv * w1.w;
    }
#pragma unroll
    for (int e = 0; e < NE_ALL; e++) {
#pragma unroll
        for (int o = 16; o > 0; o >>= 1)
            acc[e] += __shfl_xor_sync(0xffffffffu, acc[e], o);
    }
    if (lane == 0) {
        float m = acc[0]; int idx = 0;
#pragma unroll
        for (int e = 1; e < NE_ALL; e++) {
            if (acc[e] > m) { m = acc[e]; idx = e; }
        }
        float s = 0.f;
#pragma unroll
        for (int e = 0; e < NE_ALL; e++) s += expf(acc[e] - m);
        // top-1 prob = exp(0)/s ; scale = ALPHA * p1
        g_scale[gw] = ALPHA_C / s;
        g_eidx[gw]  = idx;   // may be 7 == "no routed expert"
    }
}

// ---------------------------------------------------------------------------
// Plan: bucket tokens by routed expert (idx<7 only). Single block.
// ---------------------------------------------------------------------------
__global__ void plan_kernel() {
    __shared__ int cnt[NEXP];
    __shared__ int offs[NEXP + 1];
    __shared__ int cur[NEXP];
    int tid = threadIdx.x;
    if (tid < NEXP) cnt[tid] = 0;
    __syncthreads();
    for (int t = tid; t < TOK; t += blockDim.x) {
        int e = g_eidx[t];
        if (e < NEXP) atomicAdd(&cnt[e], 1);
    }
    __syncthreads();
    if (tid == 0) {
        int o = 0;
        for (int e = 0; e < NEXP; e++) { offs[e] = o; cur[e] = o; o += cnt[e]; }
        offs[NEXP] = o;
    }
    __syncthreads();
    for (int t = tid; t < TOK; t += blockDim.x) {
        int e = g_eidx[t];
        if (e < NEXP) {
            int p = atomicAdd(&cur[e], 1);
            g_perm[p] = t;
        }
    }
    if (tid <= NEXP) g_off[tid] = offs[tid];
}

// ---------------------------------------------------------------------------
// Generic TF32 WMMA GEMM, 128x64 tile, BK=16, 8 warps (warp tile 32x32).
//
// EPI: 0 = C[row] = silu(acc)           (write h)
//      1 = C[row] = acc * C[row]        (h *= up)
//      2 = C[row] = acc                 (shared down, plain write)
//      3 = C[tok] += g_scale[tok]*acc   (routed down, scatter-add)
// GATHER_A: A rows indirected through g_perm (routed up/gate stages)
// GROUPED : per-expert row range from g_off[], weight offset e*b_stride
// ---------------------------------------------------------------------------
template <int EPI, bool GATHER_A, bool GROUPED>
__global__ __launch_bounds__(NTHREADS)
void gemm_kernel(const float* __restrict__ A,
                 const float* __restrict__ Bw,
                 float* __restrict__ C,
                 int K, int N, int M_dense,
                 long long b_stride) {
    // smem: union of {As+Bs} (main loop) and Cs (epilogue)
    __shared__ __align__(16) float smem[BM * BN];     // 32 KB
    float (*As)[BK] = reinterpret_cast<float(*)[BK]>(smem);            // 128x16
    float (*Bs)[BN] = reinterpret_cast<float(*)[BN]>(smem + BM * BK);  // 16x64
    float (*Cs)[BN] = reinterpret_cast<float(*)[BN]>(smem);            // 128x64

    int e, off, count;
    if (GROUPED) {
        e = blockIdx.z;
        off = g_off[e];
        count = g_off[e + 1] - off;
    } else {
        e = 0; off = 0; count = M_dense;
    }
    int m0 = blockIdx.x * BM;
    if (m0 >= count) return;
    int n0 = blockIdx.y * BN;

    const float* Bp = Bw + (size_t)e * (size_t)b_stride;

    int tid  = threadIdx.x;
    int warp = tid >> 5;
    int wm   = warp >> 1;   // 0..3 -> 32-row band
    int wn   = warp & 1;    // 0..1 -> 32-col band

    // Precompute the 2 A source rows this thread streams (fixed across K).
    int arow[2];
#pragma unroll
    for (int c = 0; c < 2; c++) {
        int lin = tid + c * NTHREADS;
        int r = lin >> 2;                 // 0..127
        int rr = m0 + r;
        if (rr >= count) rr = m0;         // clamp to a valid row (discarded later)
        arow[c] = GATHER_A ? g_perm[off + rr] : (off + rr);
    }
    int brow = tid >> 4;          // 0..15
    int bcol = (tid & 15) * 4;    // 0..60

    wmma::fragment<wmma::accumulator, 16, 16, 8, float> acc[2][2];
#pragma unroll
    for (int i = 0; i < 2; i++)
#pragma unroll
        for (int j = 0; j < 2; j++)
            wmma::fill_fragment(acc[i][j], 0.0f);

    for (int kt = 0; kt < K; kt += BK) {
        // ---- load A tile (128x16) : 2 x float4 per thread
#pragma unroll
        for (int c = 0; c < 2; c++) {
            int lin = tid + c * NTHREADS;
            int r   = lin >> 2;
            int kc  = (lin & 3) * 4;
            float4 v = *reinterpret_cast<const float4*>(
                A + (size_t)arow[c] * K + kt + kc);
            *reinterpret_cast<float4*>(&As[r][kc]) = v;
        }
        // ---- load B tile (16x64) : 1 x float4 per thread
        {
            float4 v = *reinterpret_cast<const float4*>(
                Bp + (size_t)(kt + brow) * N + n0 + bcol);
            *reinterpret_cast<float4*>(&Bs[brow][bcol]) = v;
        }
        __syncthreads();

#pragma unroll
        for (int k0 = 0; k0 < BK; k0 += 8) {
            wmma::fragment<wmma::matrix_a, 16, 16, 8, wmma::precision::tf32,
                           wmma::row_major> af[2];
            wmma::fragment<wmma::matrix_b, 16, 16, 8, wmma::precision::tf32,
                           wmma::row_major> bf[2];
#pragma unroll
            for (int i = 0; i < 2; i++) {
                wmma::load_matrix_sync(af[i], &As[wm * 32 + i * 16][k0], BK);
#pragma unroll
                for (int t2 = 0; t2 < af[i].num_elements; t2++)
                    af[i].x[t2] = wmma::__float_to_tf32(af[i].x[t2]);
            }
#pragma unroll
            for (int j = 0; j < 2; j++) {
                wmma::load_matrix_sync(bf[j], &Bs[k0][wn * 32 + j * 16], BN);
#pragma unroll
                for (int t2 = 0; t2 < bf[j].num_elements; t2++)
                    bf[j].x[t2] = wmma::__float_to_tf32(bf[j].x[t2]);
            }
#pragma unroll
            for (int i = 0; i < 2; i++)
#pragma unroll
                for (int j = 0; j < 2; j++)
                    wmma::mma_sync(acc[i][j], af[i], bf[j], acc[i][j]);
        }
        __syncthreads();
    }

    // ---- epilogue: stage through smem, bounds-guarded global writes
#pragma unroll
    for (int i = 0; i < 2; i++)
#pragma unroll
        for (int j = 0; j < 2; j++)
            wmma::store_matrix_sync(&Cs[wm * 32 + i * 16][wn * 32 + j * 16],
                                    acc[i][j], BN, wmma::mem_row_major);
    __syncthreads();

    for (int lin = tid; lin < BM * BN; lin += NTHREADS) {
        int r  = lin >> 6;        // /BN
        int cc = lin & 63;        // %BN
        int rr = m0 + r;
        if (rr >= count) continue;
        float v = Cs[r][cc];
        if (EPI == 0) {           // silu write
            float sv = v / (1.0f + expf(-v));
            C[(size_t)(off + rr) * N + n0 + cc] = sv;
        } else if (EPI == 1) {    // multiply into existing
            size_t a = (size_t)(off + rr) * N + n0 + cc;
            C[a] = v * C[a];
        } else if (EPI == 2) {    // plain write (shared down)
            C[(size_t)rr * N + n0 + cc] = v;
        } else {                  // routed down: scatter + scale-add
            int tok = g_perm[off + rr];
            size_t a = (size_t)tok * N + n0 + cc;
            C[a] += g_scale[tok] * v;
        }
    }
}

// ---------------------------------------------------------------------------
// Launch
// ---------------------------------------------------------------------------
extern "C" void kernel_launch(void* const* d_in, const int* in_sizes, int n_in,
                              void* d_out, int out_size) {
    const float* x       = (const float*)d_in[0];  // [1,2048,1024]
    const float* w_router= (const float*)d_in[1];  // [1024,8]
    const float* w_up    = (const float*)d_in[2];  // [7,1024,4096]
    const float* w_gate  = (const float*)d_in[3];  // [7,1024,4096]
    const float* w_down  = (const float*)d_in[4];  // [7,4096,1024]
    const float* ws_up   = (const float*)d_in[5];  // [1024,4096]
    const float* ws_gate = (const float*)d_in[6];  // [1024,4096]
    const float* ws_down = (const float*)d_in[7];  // [4096,1024]
    float* out = (float*)d_out;                    // [1,2048,1024]

    void *hr_p = nullptr, *hs_p = nullptr;
    cudaGetSymbolAddress(&hr_p, g_hr);
    cudaGetSymbolAddress(&hs_p, g_hs);
    float* hr = (float*)hr_p;
    float* hs = (float*)hs_p;

    // 1) router (fp32 exact; argmax must match reference)
    router_kernel<<<TOK / 8, 256>>>(x, w_router);
    // 2) token -> expert buckets
    plan_kernel<<<1, 256>>>();

    const long long ug_stride = (long long)DIMK * HIDN;  // up/gate expert stride
    const long long dn_stride = (long long)HIDN * DIMK;  // down expert stride

    dim3 grA_r(TOK / BM, HIDN / BN, NEXP);   // 16 x 64 x 7 (early-exit on count)
    dim3 grA_s(TOK / BM, HIDN / BN, 1);      // 16 x 64
    dim3 grB_s(TOK / BM, DIMK / BN, 1);      // 16 x 16
    dim3 grB_r(TOK / BM, DIMK / BN, NEXP);   // 16 x 16 x 7

    // 3) routed gate:  h_r = silu(x_g @ w_gate[e])
    gemm_kernel<0, true,  true ><<<grA_r, NTHREADS>>>(x,  w_gate, hr, DIMK, HIDN, 0, ug_stride);
    // 4) routed up:    h_r *= (x_g @ w_up[e])
    gemm_kernel<1, true,  true ><<<grA_r, NTHREADS>>>(x,  w_up,   hr, DIMK, HIDN, 0, ug_stride);
    // 5) shared gate:  h_s = silu(x @ ws_gate)
    gemm_kernel<0, false, false><<<grA_s, NTHREADS>>>(x,  ws_gate, hs, DIMK, HIDN, TOK, 0);
    // 6) shared up:    h_s *= (x @ ws_up)
    gemm_kernel<1, false, false><<<grA_s, NTHREADS>>>(x,  ws_up,   hs, DIMK, HIDN, TOK, 0);
    // 7) shared down:  out = h_s @ ws_down          (writes every element)
    gemm_kernel<2, false, false><<<grB_s, NTHREADS>>>(hs, ws_down, out, HIDN, DIMK, TOK, 0);
    // 8) routed down:  out[tok] += scale[tok] * (h_r @ w_down[e])
    gemm_kernel<3, false, true ><<<grB_r, NTHREADS>>>(hr, w_down,  out, HIDN, DIMK, 0, dn_stride);
}

// round 2
// speedup vs baseline: 1.4234x; 1.4234x over previous
#include <cuda_runtime.h>
#include <mma.h>
#include <math.h>
#include <stdint.h>

using namespace nvcuda;

// ---------------------------------------------------------------------------
// Problem constants
// ---------------------------------------------------------------------------
#define TOK   2048
#define DIMK  1024
#define HIDN  4096
#define NEXP  7
#define NE_ALL 8
#define ALPHA_C 2.0f

#define BM 128
#define NTHREADS 256

// ---------------------------------------------------------------------------
// Scratch
// ---------------------------------------------------------------------------
__device__ int   g_eidx[TOK];
__device__ float g_scale[TOK];
__device__ int   g_perm[TOK];
__device__ int   g_off[NEXP + 1];
__device__ float g_hr[(size_t)TOK * HIDN];   // routed hidden (perm-position rows)
__device__ float g_hs[(size_t)TOK * HIDN];   // shared hidden (token rows)

// ---------------------------------------------------------------------------
// cp.async helpers
// ---------------------------------------------------------------------------
__device__ __forceinline__ void cp_async16(void* smem_dst, const void* gmem_src) {
    uint32_t s = (uint32_t)__cvta_generic_to_shared(smem_dst);
    asm volatile("cp.async.cg.shared.global [%0], [%1], 16;\n" :: "r"(s), "l"(gmem_src));
}
__device__ __forceinline__ void cp_commit() {
    asm volatile("cp.async.commit_group;\n");
}
template <int N>
__device__ __forceinline__ void cp_wait() {
    asm volatile("cp.async.wait_group %0;\n" :: "n"(N));
}

__device__ __forceinline__ float silu_f(float v) {
    return v / (1.0f + expf(-v));
}

// ---------------------------------------------------------------------------
// Router: fp32-exact logits, softmax top-1. One warp per token.
// ---------------------------------------------------------------------------
__global__ void router_kernel(const float* __restrict__ x,
                              const float* __restrict__ wr) {
    int gw   = (blockIdx.x * blockDim.x + threadIdx.x) >> 5;
    int lane = threadIdx.x & 31;
    if (gw >= TOK) return;
    const float* xr = x + (size_t)gw * DIMK;

    float acc[NE_ALL];
#pragma unroll
    for (int e = 0; e < NE_ALL; e++) acc[e] = 0.f;

    for (int d = lane; d < DIMK; d += 32) {
        float xv = xr[d];
        const float4* w4 = reinterpret_cast<const float4*>(wr + (size_t)d * NE_ALL);
        float4 w0 = w4[0];
        float4 w1 = w4[1];
        acc[0] += xv * w0.x; acc[1] += xv * w0.y;
        acc[2] += xv * w0.z; acc[3] += xv * w0.w;
        acc[4] += xv * w1.x; acc[5] += xv * w1.y;
        acc[6] += xv * w1.z; acc[7] += xv * w1.w;
    }
#pragma unroll
    for (int e = 0; e < NE_ALL; e++) {
#pragma unroll
        for (int o = 16; o > 0; o >>= 1)
            acc[e] += __shfl_xor_sync(0xffffffffu, acc[e], o);
    }
    if (lane == 0) {
        float m = acc[0]; int idx = 0;
#pragma unroll
        for (int e = 1; e < NE_ALL; e++)
            if (acc[e] > m) { m = acc[e]; idx = e; }
        float s = 0.f;
#pragma unroll
        for (int e = 0; e < NE_ALL; e++) s += expf(acc[e] - m);
        g_scale[gw] = ALPHA_C / s;     // ALPHA * top1 prob
        g_eidx[gw]  = idx;             // may be 7 == no routed expert
    }
}

// ---------------------------------------------------------------------------
// Plan: bucket tokens by routed expert (idx<7 only). Single block.
// ---------------------------------------------------------------------------
__global__ void plan_kernel() {
    __shared__ int cnt[NEXP];
    __shared__ int offs[NEXP + 1];
    __shared__ int cur[NEXP];
    int tid = threadIdx.x;
    if (tid < NEXP) cnt[tid] = 0;
    __syncthreads();
    for (int t = tid; t < TOK; t += blockDim.x) {
        int e = g_eidx[t];
        if (e < NEXP) atomicAdd(&cnt[e], 1);
    }
    __syncthreads();
    if (tid == 0) {
        int o = 0;
        for (int e = 0; e < NEXP; e++) { offs[e] = o; cur[e] = o; o += cnt[e]; }
        offs[NEXP] = o;
    }
    __syncthreads();
    for (int t = tid; t < TOK; t += blockDim.x) {
        int e = g_eidx[t];
        if (e < NEXP) {
            int p = atomicAdd(&cur[e], 1);
            g_perm[p] = t;
        }
    }
    if (tid <= NEXP) g_off[tid] = offs[tid];
}

// ---------------------------------------------------------------------------
// Fused hidden kernel:  H = silu(A@Bg) * (A@Bu)
// Block tile 128 x 64, dual B, BK=32, 2-stage cp.async pipeline.
// 8 warps, layout 4x2, warp tile 32x32 per output.
// ---------------------------------------------------------------------------
#define H_BK 32
#define H_AP 36                    // A smem pitch (floats)
#define H_BP 68                    // B smem pitch (floats)
#define H_ASZ (128 * H_AP)         // 4608
#define H_BSZ (H_BK * H_BP)        // 2176 (per B tile)
#define H_STG (H_ASZ + 2 * H_BSZ)  // 8960 floats per stage

template <bool GATHER_A, bool GROUPED>
__global__ __launch_bounds__(NTHREADS, 2)
void hidden_kernel(const float* __restrict__ A,
                   const float* __restrict__ Bg,
                   const float* __restrict__ Bu,
                   float* __restrict__ H,
                   int M_dense, long long b_stride) {
    extern __shared__ __align__(16) float smem[];
    const int K = DIMK, N = HIDN;

    int e, off, count;
    if (GROUPED) { e = blockIdx.z; off = g_off[e]; count = g_off[e + 1] - off; }
    else         { e = 0; off = 0; count = M_dense; }
    int m0 = blockIdx.x * BM;
    if (m0 >= count) return;
    int n0 = blockIdx.y * 64;

    const float* BgP = Bg + (size_t)e * (size_t)b_stride;
    const float* BuP = Bu + (size_t)e * (size_t)b_stride;

    int tid  = threadIdx.x;
    int warp = tid >> 5;
    int wm   = warp >> 1;    // 0..3
    int wn   = warp & 1;     // 0..1

    // A row assignment: 4 rows per thread (fixed across K)
    int arow[4];
#pragma unroll
    for (int c = 0; c < 4; c++) {
        int lin = tid + c * NTHREADS;
        int r = lin >> 3;                    // 0..127
        int rr = m0 + r;
        if (rr >= count) rr = m0;
        arow[c] = GATHER_A ? g_perm[off + rr] : (off + rr);
    }

    auto load_stage = [&](int kt, int s) {
        float* As = smem + s * H_STG;
        float* Bs = As + H_ASZ;
#pragma unroll
        for (int c = 0; c < 4; c++) {
            int lin = tid + c * NTHREADS;
            int r   = lin >> 3;
            int kc  = (lin & 7) * 4;
            cp_async16(&As[r * H_AP + kc],
                       A + (size_t)arow[c] * K + kt + kc);
        }
#pragma unroll
        for (int c = 0; c < 4; c++) {
            int lin = tid + c * NTHREADS;
            int t2  = lin >> 9;              // 0: gate, 1: up
            int w   = lin & 511;
            int br  = w >> 4;                // 0..31
            int bc  = (w & 15) * 4;          // 0..60
            const float* src = (t2 == 0 ? BgP : BuP)
                               + (size_t)(kt + br) * N + n0 + bc;
            cp_async16(&Bs[t2 * H_BSZ + br * H_BP + bc], src);
        }
    };

    wmma::fragment<wmma::accumulator, 16, 16, 8, float> accg[2][2], accu[2][2];
#pragma unroll
    for (int i = 0; i < 2; i++)
#pragma unroll
        for (int j = 0; j < 2; j++) {
            wmma::fill_fragment(accg[i][j], 0.0f);
            wmma::fill_fragment(accu[i][j], 0.0f);
        }

    const int nk = K / H_BK;   // 32
    load_stage(0, 0);
    cp_commit();

    for (int kt = 0; kt < nk; kt++) {
        if (kt + 1 < nk) {
            load_stage((kt + 1) * H_BK, (kt + 1) & 1);
            cp_commit();
            cp_wait<1>();
        } else {
            cp_wait<0>();
        }
        __syncthreads();

        float* As = smem + (kt & 1) * H_STG;
        float* Bs = As + H_ASZ;

#pragma unroll
        for (int k0 = 0; k0 < H_BK; k0 += 8) {
            wmma::fragment<wmma::matrix_a, 16, 16, 8, wmma::precision::tf32,
                           wmma::row_major> a[2];
            wmma::fragment<wmma::matrix_b, 16, 16, 8, wmma::precision::tf32,
                           wmma::row_major> bg[2], bu[2];
#pragma unroll
            for (int i = 0; i < 2; i++) {
                wmma::load_matrix_sync(a[i], &As[(wm * 32 + i * 16) * H_AP + k0], H_AP);
#pragma unroll
                for (int t = 0; t < a[i].num_elements; t++)
                    a[i].x[t] = wmma::__float_to_tf32(a[i].x[t]);
            }
#pragma unroll
            for (int j = 0; j < 2; j++) {
                wmma::load_matrix_sync(bg[j], &Bs[0 * H_BSZ + k0 * H_BP + wn * 32 + j * 16], H_BP);
                wmma::load_matrix_sync(bu[j], &Bs[1 * H_BSZ + k0 * H_BP + wn * 32 + j * 16], H_BP);
#pragma unroll
                for (int t = 0; t < bg[j].num_elements; t++) {
                    bg[j].x[t] = wmma::__float_to_tf32(bg[j].x[t]);
                    bu[j].x[t] = wmma::__float_to_tf32(bu[j].x[t]);
                }
            }
#pragma unroll
            for (int i = 0; i < 2; i++)
#pragma unroll
                for (int j = 0; j < 2; j++) {
                    wmma::mma_sync(accg[i][j], a[i], bg[j], accg[i][j]);
                    wmma::mma_sync(accu[i][j], a[i], bu[j], accu[i][j]);
                }
        }
        __syncthreads();
    }

    // epilogue: h = silu(g) * u   (computed in registers, same frag layout)
#pragma unroll
    for (int i = 0; i < 2; i++)
#pragma unroll
        for (int j = 0; j < 2; j++)
#pragma unroll
            for (int t = 0; t < accg[i][j].num_elements; t++)
                accg[i][j].x[t] = silu_f(accg[i][j].x[t]) * accu[i][j].x[t];

    if (m0 + BM <= count) {
        // full tile: store fragments straight to global
#pragma unroll
        for (int i = 0; i < 2; i++)
#pragma unroll
            for (int j = 0; j < 2; j++)
                wmma::store_matrix_sync(
                    H + (size_t)(off + m0 + wm * 32 + i * 16) * N + n0 + wn * 32 + j * 16,
                    accg[i][j], N, wmma::mem_row_major);
    } else {
        // tail tile: stage through smem, guarded writes
        __syncthreads();
        float* Cs = smem;   // 128 x 68
#pragma unroll
        for (int i = 0; i < 2; i++)
#pragma unroll
            for (int j = 0; j < 2; j++)
                wmma::store_matrix_sync(&Cs[(wm * 32 + i * 16) * 68 + wn * 32 + j * 16],
                                        accg[i][j], 68, wmma::mem_row_major);
        __syncthreads();
        for (int lin = tid; lin < 128 * 64; lin += NTHREADS) {
            int r  = lin >> 6;
            int cc = lin & 63;
            if (m0 + r >= count) continue;
            H[(size_t)(off + m0 + r) * N + n0 + cc] = Cs[r * 68 + cc];
        }
    }
}

// ---------------------------------------------------------------------------
// Down-projection kernel: C-tile 128x128, BK=32, 2-stage cp.async.
// 8 warps 2x4, warp tile 64x32 (acc 4x2).
// EPI 2: C[row] = acc (plain write, M multiple of 128)
// EPI 3: C[perm[row]] += g_scale[perm[row]] * acc (scatter-add, staged)
// ---------------------------------------------------------------------------
#define D_BK 32
#define D_AP 36
#define D_BP 132
#define D_ASZ (128 * D_AP)          // 4608
#define D_BSZ (D_BK * D_BP)         // 4224
#define D_STG (D_ASZ + D_BSZ)       // 8832 floats per stage

template <int EPI, bool GROUPED>
__global__ __launch_bounds__(NTHREADS, 2)
void down_kernel(const float* __restrict__ A,
                 const float* __restrict__ Bw,
                 float* __restrict__ C,
                 int M_dense, long long b_stride) {
    extern __shared__ __align__(16) float smem[];
    const int K = HIDN, N = DIMK;

    int e, off, count;
    if (GROUPED) { e = blockIdx.z; off = g_off[e]; count = g_off[e + 1] - off; }
    else         { e = 0; off = 0; count = M_dense; }
    int m0 = blockIdx.x * BM;
    if (m0 >= count) return;
    int n0 = blockIdx.y * 128;

    const float* Bp = Bw + (size_t)e * (size_t)b_stride;

    int tid  = threadIdx.x;
    int warp = tid >> 5;
    int wm   = warp >> 2;    // 0..1 (64-row band)
    int wn   = warp & 3;     // 0..3 (32-col band)

    int arow[4];
#pragma unroll
    for (int c = 0; c < 4; c++) {
        int lin = tid + c * NTHREADS;
        int r = lin >> 3;
        int rr = m0 + r;
        if (rr >= count) rr = m0;
        arow[c] = off + rr;          // A is hr/hs: direct row (perm-position)
    }

    auto load_stage = [&](int kt, int s) {
        float* As = smem + s * D_STG;
        float* Bs = As + D_ASZ;
#pragma unroll
        for (int c = 0; c < 4; c++) {
            int lin = tid + c * NTHREADS;
            int r   = lin >> 3;
            int kc  = (lin & 7) * 4;
            cp_async16(&As[r * D_AP + kc],
                       A + (size_t)arow[c] * K + kt + kc);
        }
#pragma unroll
        for (int c = 0; c < 4; c++) {
            int lin = tid + c * NTHREADS;
            int br  = lin >> 5;                // 0..31
            int bc  = (lin & 31) * 4;          // 0..124
            cp_async16(&Bs[br * D_BP + bc],
                       Bp + (size_t)(kt + br) * N + n0 + bc);
        }
    };

    wmma::fragment<wmma::accumulator, 16, 16, 8, float> acc[4][2];
#pragma unroll
    for (int i = 0; i < 4; i++)
#pragma unroll
        for (int j = 0; j < 2; j++)
            wmma::fill_fragment(acc[i][j], 0.0f);

    const int nk = K / D_BK;   // 128
    load_stage(0, 0);
    cp_commit();

    for (int kt = 0; kt < nk; kt++) {
        if (kt + 1 < nk) {
            load_stage((kt + 1) * D_BK, (kt + 1) & 1);
            cp_commit();
            cp_wait<1>();
        } else {
            cp_wait<0>();
        }
        __syncthreads();

        float* As = smem + (kt & 1) * D_STG;
        float* Bs = As + D_ASZ;

#pragma unroll
        for (int k0 = 0; k0 < D_BK; k0 += 8) {
            wmma::fragment<wmma::matrix_a, 16, 16, 8, wmma::precision::tf32,
                           wmma::row_major> a[4];
            wmma::fragment<wmma::matrix_b, 16, 16, 8, wmma::precision::tf32,
                           wmma::row_major> b[2];
#pragma unroll
            for (int i = 0; i < 4; i++) {
                wmma::load_matrix_sync(a[i], &As[(wm * 64 + i * 16) * D_AP + k0], D_AP);
#pragma unroll
                for (int t = 0; t < a[i].num_elements; t++)
                    a[i].x[t] = wmma::__float_to_tf32(a[i].x[t]);
            }
#pragma unroll
            for (int j = 0; j < 2; j++) {
                wmma::load_matrix_sync(b[j], &Bs[k0 * D_BP + wn * 32 + j * 16], D_BP);
#pragma unroll
                for (int t = 0; t < b[j].num_elements; t++)
                    b[j].x[t] = wmma::__float_to_tf32(b[j].x[t]);
            }
#pragma unroll
            for (int i = 0; i < 4; i++)
#pragma unroll
                for (int j = 0; j < 2; j++)
                    wmma::mma_sync(acc[i][j], a[i], b[j], acc[i][j]);
        }
        __syncthreads();
    }

    if (EPI == 2) {
        // dense write (M multiple of 128 for shared path)
#pragma unroll
        for (int i = 0; i < 4; i++)
#pragma unroll
            for (int j = 0; j < 2; j++)
                wmma::store_matrix_sync(
                    C + (size_t)(m0 + wm * 64 + i * 16) * N + n0 + wn * 32 + j * 16,
                    acc[i][j], N, wmma::mem_row_major);
    } else {
        // scatter-add with per-token scale: stage through smem
        __syncthreads();
        float* Cs = smem;   // 128 x 132
#pragma unroll
        for (int i = 0; i < 4; i++)
#pragma unroll
            for (int j = 0; j < 2; j++)
                wmma::store_matrix_sync(&Cs[(wm * 64 + i * 16) * D_BP + wn * 32 + j * 16],
                                        acc[i][j], D_BP, wmma::mem_row_major);
        __syncthreads();
        for (int lin = tid; lin < 128 * 128; lin += NTHREADS) {
            int r  = lin >> 7;
            int cc = lin & 127;
            if (m0 + r >= count) continue;
            int tok = g_perm[off + m0 + r];
            size_t a = (size_t)tok * N + n0 + cc;
            C[a] += g_scale[tok] * Cs[r * D_BP + cc];
        }
    }
}

// ---------------------------------------------------------------------------
// Launch
// ---------------------------------------------------------------------------
extern "C" void kernel_launch(void* const* d_in, const int* in_sizes, int n_in,
                              void* d_out, int out_size) {
    const float* x        = (const float*)d_in[0];
    const float* w_router = (const float*)d_in[1];
    const float* w_up     = (const float*)d_in[2];
    const float* w_gate   = (const float*)d_in[3];
    const float* w_down   = (const float*)d_in[4];
    const float* ws_up    = (const float*)d_in[5];
    const float* ws_gate  = (const float*)d_in[6];
    const float* ws_down  = (const float*)d_in[7];
    float* out = (float*)d_out;

    void *hr_p = nullptr, *hs_p = nullptr;
    cudaGetSymbolAddress(&hr_p, g_hr);
    cudaGetSymbolAddress(&hs_p, g_hs);
    float* hr = (float*)hr_p;
    float* hs = (float*)hs_p;

    const int h_smem = 2 * H_STG * (int)sizeof(float);   // 71680 B
    const int d_smem = 2 * D_STG * (int)sizeof(float);   // 70656 B
    cudaFuncSetAttribute(hidden_kernel<true,  true >,
                         cudaFuncAttributeMaxDynamicSharedMemorySize, h_smem);
    cudaFuncSetAttribute(hidden_kernel<false, false>,
                         cudaFuncAttributeMaxDynamicSharedMemorySize, h_smem);
    cudaFuncSetAttribute(down_kernel<2, false>,
                         cudaFuncAttributeMaxDynamicSharedMemorySize, d_smem);
    cudaFuncSetAttribute(down_kernel<3, true >,
                         cudaFuncAttributeMaxDynamicSharedMemorySize, d_smem);

    router_kernel<<<TOK / 8, 256>>>(x, w_router);
    plan_kernel<<<1, 256>>>();

    const long long ug_stride = (long long)DIMK * HIDN;
    const long long dn_stride = (long long)HIDN * DIMK;

    dim3 grH_r(TOK / BM, HIDN / 64, NEXP);   // 16 x 64 x 7 (early-exit on count)
    dim3 grH_s(TOK / BM, HIDN / 64, 1);
    dim3 grD_s(TOK / BM, DIMK / 128, 1);     // 16 x 8
    dim3 grD_r(TOK / BM, DIMK / 128, NEXP);  // 16 x 8 x 7

    // routed hidden: hr = silu(xg @ Wg[e]) * (xg @ Wu[e])
    hidden_kernel<true,  true ><<<grH_r, NTHREADS, h_smem>>>(x, w_gate, w_up, hr, 0, ug_stride);
    // shared hidden: hs = silu(x @ Wsg) * (x @ Wsu)
    hidden_kernel<false, false><<<grH_s, NTHREADS, h_smem>>>(x, ws_gate, ws_up, hs, TOK, 0);
    // shared down: out = hs @ Wsd
    down_kernel<2, false><<<grD_s, NTHREADS, d_smem>>>(hs, ws_down, out, TOK, 0);
    // routed down: out[tok] += scale[tok] * (hr @ Wd[e])
    down_kernel<3, true ><<<grD_r, NTHREADS, d_smem>>>(hr, w_down, out, 0, dn_stride);
}